// round 1
// baseline (speedup 1.0000x reference)
#include <cuda_runtime.h>
#include <math.h>

#define BLOCKT  256
#define KDIM    784
#define KPAD    800
#define TILE_K  32
#define NTILES  25          // 25*32 = 800 (zero-padded past 784)
#define XSTRIDE 36          // 32 + 4 pad -> conflict-free float4 LDS/STS

// smem floats: xs[256*36] + w1s[800*4] + sw[240]
#define SMEM_FLOATS (BLOCKT*XSTRIDE + KPAD*4 + 240)

__global__ void __launch_bounds__(BLOCKT) qhybrid_kernel(
    const float* __restrict__ x,
    const float* __restrict__ W1, const float* __restrict__ b1,
    const float* __restrict__ qw,
    const float* __restrict__ W2, const float* __restrict__ b2,
    const float* __restrict__ W3, const float* __restrict__ b3,
    float* __restrict__ out, int B)
{
    extern __shared__ float smem[];
    float* xs  = smem;                    // [256][36]
    float* w1s = smem + BLOCKT*XSTRIDE;   // [800][4]
    float* sw  = w1s + KPAD*4;            // small weights

    const int tid = threadIdx.x;

    // ---- preload W1 (zero-padded rows 784..799) ----
    for (int r = tid; r < KPAD; r += BLOCKT) {
        float4 v = make_float4(0.f, 0.f, 0.f, 0.f);
        if (r < KDIM) v = __ldg((const float4*)W1 + r);
        ((float4*)w1s)[r] = v;
    }
    // ---- preload small weights: b1@0(4) qw@4(8) W2@12(128) b2@140(32) W3@172(64) b3@236(2) ----
    if (tid < 4)   sw[tid]       = b1[tid];
    if (tid < 8)   sw[4 + tid]   = qw[tid];
    if (tid < 128) sw[12 + tid]  = W2[tid];
    if (tid < 32)  sw[140 + tid] = b2[tid];
    if (tid < 64)  sw[172 + tid] = W3[tid];
    if (tid < 2)   sw[236 + tid] = b3[tid];

    const long sbase = (long)blockIdx.x * BLOCKT;
    const int  sl    = tid >> 3;        // 0..31 : sample row for staging
    const int  j4c   = (tid & 7) * 4;   // float4 column within tile

    float acc[4] = {0.f, 0.f, 0.f, 0.f};

    // ---- GEMM: pre = x @ W1 (tiled through smem) ----
    for (int kt = 0; kt < NTILES; kt++) {
        const int colbase = kt * TILE_K;
        const int col = colbase + j4c;
        #pragma unroll
        for (int i = 0; i < 8; i++) {
            int s = sl + i * 32;
            long sg = sbase + s;
            float4 v = make_float4(0.f, 0.f, 0.f, 0.f);
            if (col < KDIM && sg < (long)B)
                v = *(const float4*)(x + sg * KDIM + col);
            *(float4*)(xs + s * XSTRIDE + j4c) = v;
        }
        __syncthreads();
        const float* xr = xs + tid * XSTRIDE;
        #pragma unroll
        for (int jj = 0; jj < 8; jj++) {
            float4 xv = *(const float4*)(xr + jj * 4);
            const float* wp = w1s + (colbase + jj * 4) * 4;
            float4 wa = *(const float4*)(wp);
            float4 wb = *(const float4*)(wp + 4);
            float4 wc = *(const float4*)(wp + 8);
            float4 wd = *(const float4*)(wp + 12);
            acc[0] = fmaf(xv.x, wa.x, acc[0]); acc[1] = fmaf(xv.x, wa.y, acc[1]);
            acc[2] = fmaf(xv.x, wa.z, acc[2]); acc[3] = fmaf(xv.x, wa.w, acc[3]);
            acc[0] = fmaf(xv.y, wb.x, acc[0]); acc[1] = fmaf(xv.y, wb.y, acc[1]);
            acc[2] = fmaf(xv.y, wb.z, acc[2]); acc[3] = fmaf(xv.y, wb.w, acc[3]);
            acc[0] = fmaf(xv.z, wc.x, acc[0]); acc[1] = fmaf(xv.z, wc.y, acc[1]);
            acc[2] = fmaf(xv.z, wc.z, acc[2]); acc[3] = fmaf(xv.z, wc.w, acc[3]);
            acc[0] = fmaf(xv.w, wd.x, acc[0]); acc[1] = fmaf(xv.w, wd.y, acc[1]);
            acc[2] = fmaf(xv.w, wd.z, acc[2]); acc[3] = fmaf(xv.w, wd.w, acc[3]);
        }
        __syncthreads();
    }

    // ---- angles = relu(pre + b1) ----
    float cq[4], sq[4];
    #pragma unroll
    for (int q = 0; q < 4; q++) {
        float ang = fmaxf(acc[q] + sw[q], 0.f);
        __sincosf(0.5f * ang, &sq[q], &cq[q]);
    }

    // ---- 4-qubit statevector in registers ----
    // flat index i: bit for wire q at position (3-q). amp[i] = prod_q (bit? -i*sin : cos)
    float re[16], im[16];
    #pragma unroll
    for (int i = 0; i < 16; i++) {
        float m = 1.f;
        #pragma unroll
        for (int q = 0; q < 4; q++) m *= ((i >> (3 - q)) & 1) ? sq[q] : cq[q];
        int k = __popc(i) & 3;  // phase (-i)^k
        re[i] = (k == 0) ? m : ((k == 2) ? -m : 0.f);
        im[i] = (k == 1) ? -m : ((k == 3) ? m : 0.f);
    }

    // ---- BasicEntanglerLayers: RX(w[l,q]) then CNOT ring ----
    #pragma unroll
    for (int l = 0; l < 2; l++) {
        #pragma unroll
        for (int q = 0; q < 4; q++) {
            float cg, sg;
            __sincosf(0.5f * sw[4 + l * 4 + q], &sg, &cg);
            const int mask = 8 >> q;
            #pragma unroll
            for (int i = 0; i < 16; i++) {
                if (i & mask) continue;
                const int i1 = i | mask;
                float r0 = re[i], ii0 = im[i], r1 = re[i1], ii1 = im[i1];
                re[i]  = fmaf(cg, r0,  sg * ii1);
                im[i]  = fmaf(cg, ii0, -sg * r1);
                re[i1] = fmaf(cg, r1,  sg * ii0);
                im[i1] = fmaf(cg, ii1, -sg * r0);
            }
        }
        #pragma unroll
        for (int q = 0; q < 4; q++) {
            const int cmask = 8 >> q;
            const int tmask = 8 >> ((q + 1) & 3);
            #pragma unroll
            for (int i = 0; i < 16; i++) {
                if ((i & cmask) && !(i & tmask)) {
                    const int j = i | tmask;
                    float t = re[i]; re[i] = re[j]; re[j] = t;
                    t = im[i]; im[i] = im[j]; im[j] = t;
                }
            }
        }
    }

    // ---- <Z_q> expectation values ----
    float ez[4] = {0.f, 0.f, 0.f, 0.f};
    #pragma unroll
    for (int i = 0; i < 16; i++) {
        float p = re[i] * re[i] + im[i] * im[i];
        #pragma unroll
        for (int q = 0; q < 4; q++)
            ez[q] += ((i >> (3 - q)) & 1) ? -p : p;
    }
    #pragma unroll
    for (int q = 0; q < 4; q++)
        if (!(ez[q] == ez[q])) ez[q] = 0.f;  // NaN -> 0 (matches reference)

    // ---- post = relu(ez@W2 + b2); logits = post@W3 + b3; softmax ----
    float l0 = sw[236], l1 = sw[237];
    #pragma unroll
    for (int j = 0; j < 32; j++) {
        float pj = sw[140 + j];
        #pragma unroll
        for (int q = 0; q < 4; q++)
            pj = fmaf(ez[q], sw[12 + q * 32 + j], pj);
        pj = fmaxf(pj, 0.f);
        l0 = fmaf(pj, sw[172 + j * 2],     l0);
        l1 = fmaf(pj, sw[172 + j * 2 + 1], l1);
    }
    float mx = fmaxf(l0, l1);
    float e0 = __expf(l0 - mx);
    float e1 = __expf(l1 - mx);
    float inv = 1.f / (e0 + e1);

    long sg = sbase + tid;
    if (sg < (long)B) {
        float2 o = make_float2(e0 * inv, e1 * inv);
        *(float2*)(out + sg * 2) = o;
    }
}

extern "C" void kernel_launch(void* const* d_in, const int* in_sizes, int n_in,
                              void* d_out, int out_size) {
    const float* x  = (const float*)d_in[0];
    const float* W1 = (const float*)d_in[1];
    const float* b1 = (const float*)d_in[2];
    const float* qw = (const float*)d_in[3];
    const float* W2 = (const float*)d_in[4];
    const float* b2 = (const float*)d_in[5];
    const float* W3 = (const float*)d_in[6];
    const float* b3 = (const float*)d_in[7];
    float* out = (float*)d_out;

    int B = in_sizes[0] / KDIM;
    int grid = (B + BLOCKT - 1) / BLOCKT;
    size_t smem_bytes = SMEM_FLOATS * sizeof(float);  // ~50.6 KB -> needs opt-in
    cudaFuncSetAttribute(qhybrid_kernel,
                         cudaFuncAttributeMaxDynamicSharedMemorySize,
                         (int)smem_bytes);
    qhybrid_kernel<<<grid, BLOCKT, smem_bytes>>>(x, W1, b1, qw, W2, b2, W3, b3, out, B);
}

// round 3
// speedup vs baseline: 1.6050x; 1.6050x over previous
#include <cuda_runtime.h>
#include <cstdint>
#include <math.h>

#define BLOCKT  128
#define KDIM    784
#define KPAD    800
#define TILE_K  32
#define NTILES  25          // 25*32 = 800 (zero-padded past 784)
#define XSTRIDE 36          // 32 + 4 pad -> conflict-free float4 LDS per 8-lane phase
#define BUFSZ   (BLOCKT*XSTRIDE)   // 4608 floats per buffer

// smem floats: xs[2][BUFSZ] + w1s[800*4] + sw[240]
#define SMEM_FLOATS (2*BUFSZ + KPAD*4 + 240)

__device__ __forceinline__ void cp_async16(unsigned dst, const float* src, int src_sz) {
    asm volatile("cp.async.cg.shared.global [%0], [%1], 16, %2;\n"
                 :: "r"(dst), "l"(src), "r"(src_sz));
}
__device__ __forceinline__ void cp_commit() {
    asm volatile("cp.async.commit_group;\n" ::: "memory");
}
template<int N>
__device__ __forceinline__ void cp_wait() {
    asm volatile("cp.async.wait_group %0;\n" :: "n"(N) : "memory");
}

__global__ void __launch_bounds__(BLOCKT) qhybrid_kernel(
    const float* __restrict__ x,
    const float* __restrict__ W1, const float* __restrict__ b1,
    const float* __restrict__ qw,
    const float* __restrict__ W2, const float* __restrict__ b2,
    const float* __restrict__ W3, const float* __restrict__ b3,
    float* __restrict__ out, int B)
{
    extern __shared__ float smem[];
    float* xs  = smem;                 // [2][128][36]
    float* w1s = smem + 2 * BUFSZ;     // [800][4]
    float* sw  = w1s + KPAD * 4;       // small weights

    const int tid = threadIdx.x;
    const long sbase = (long)blockIdx.x * BLOCKT;
    const int  sl  = tid >> 3;         // 0..15 : sample row (staging)
    const int  j4c = (tid & 7) * 4;    // float4 column within tile

    const unsigned xs_u32 = (unsigned)__cvta_generic_to_shared(xs);
    const unsigned dst0   = xs_u32 + (unsigned)((sl * XSTRIDE + j4c) * 4);

    // ---- issue cp.async for tile 0 FIRST (get DRAM going immediately) ----
    {
        const int col = j4c;                       // kt = 0, always < 784
        const float* src = x + (sbase + sl) * (long)KDIM + col;
        #pragma unroll
        for (int i = 0; i < 8; i++) {
            long sg = sbase + sl + i * 16;
            int sz = (sg < (long)B) ? 16 : 0;
            cp_async16(dst0 + (unsigned)(i * 16 * XSTRIDE * 4), src + (long)i * 16 * KDIM, sz);
        }
        cp_commit();
    }

    // ---- preload W1 (zero-padded rows 784..799) ----
    for (int r = tid; r < KPAD; r += BLOCKT) {
        float4 v = make_float4(0.f, 0.f, 0.f, 0.f);
        if (r < KDIM) v = __ldg((const float4*)W1 + r);
        ((float4*)w1s)[r] = v;
    }
    // ---- small weights: b1@0(4) qw@4(8) W2@12(128) b2@140(32) W3@172(64) b3@236(2) ----
    if (tid < 4)   sw[tid]       = b1[tid];
    if (tid < 8)   sw[4 + tid]   = qw[tid];
    if (tid < 128) sw[12 + tid]  = W2[tid];
    if (tid < 32)  sw[140 + tid] = b2[tid];
    if (tid < 64)  sw[172 + tid] = W3[tid];
    if (tid < 2)   sw[236 + tid] = b3[tid];

    float acc[4] = {0.f, 0.f, 0.f, 0.f};

    // ---- GEMM mainloop: double-buffered cp.async pipeline ----
    #pragma unroll 1
    for (int kt = 0; kt < NTILES; kt++) {
        // prefetch tile kt+1 into the other buffer
        if (kt + 1 < NTILES) {
            const int col = (kt + 1) * TILE_K + j4c;
            const int csz = (col < KDIM) ? 16 : 0;   // zero-fill tail cols of tile 24
            const float* src = x + (sbase + sl) * (long)KDIM + col;
            const unsigned d = dst0 + (unsigned)(((kt + 1) & 1) * BUFSZ * 4);
            #pragma unroll
            for (int i = 0; i < 8; i++) {
                long sg = sbase + sl + i * 16;
                int sz = (sg < (long)B) ? csz : 0;
                cp_async16(d + (unsigned)(i * 16 * XSTRIDE * 4), src + (long)i * 16 * KDIM, sz);
            }
            cp_commit();
            cp_wait<1>();     // tile kt complete (tile kt+1 still in flight)
        } else {
            cp_wait<0>();
        }
        __syncthreads();      // tile kt visible to all threads

        const float* xr = xs + (kt & 1) * BUFSZ + tid * XSTRIDE;
        const int colbase = kt * TILE_K;
        #pragma unroll
        for (int jj = 0; jj < 8; jj++) {
            float4 xv = *(const float4*)(xr + jj * 4);
            const float* wp = w1s + (colbase + jj * 4) * 4;
            float4 wa = *(const float4*)(wp);
            float4 wb = *(const float4*)(wp + 4);
            float4 wc = *(const float4*)(wp + 8);
            float4 wd = *(const float4*)(wp + 12);
            acc[0] = fmaf(xv.x, wa.x, acc[0]); acc[1] = fmaf(xv.x, wa.y, acc[1]);
            acc[2] = fmaf(xv.x, wa.z, acc[2]); acc[3] = fmaf(xv.x, wa.w, acc[3]);
            acc[0] = fmaf(xv.y, wb.x, acc[0]); acc[1] = fmaf(xv.y, wb.y, acc[1]);
            acc[2] = fmaf(xv.y, wb.z, acc[2]); acc[3] = fmaf(xv.y, wb.w, acc[3]);
            acc[0] = fmaf(xv.z, wc.x, acc[0]); acc[1] = fmaf(xv.z, wc.y, acc[1]);
            acc[2] = fmaf(xv.z, wc.z, acc[2]); acc[3] = fmaf(xv.z, wc.w, acc[3]);
            acc[0] = fmaf(xv.w, wd.x, acc[0]); acc[1] = fmaf(xv.w, wd.y, acc[1]);
            acc[2] = fmaf(xv.w, wd.z, acc[2]); acc[3] = fmaf(xv.w, wd.w, acc[3]);
        }
        __syncthreads();      // all reads of buffer kt&1 done before it is re-filled
    }

    // ---- angles = relu(pre + b1) ----
    float cq[4], sq[4];
    #pragma unroll
    for (int q = 0; q < 4; q++) {
        float ang = fmaxf(acc[q] + sw[q], 0.f);
        __sincosf(0.5f * ang, &sq[q], &cq[q]);
    }

    // ---- 4-qubit statevector in registers ----
    float re[16], im[16];
    #pragma unroll
    for (int i = 0; i < 16; i++) {
        float m = 1.f;
        #pragma unroll
        for (int q = 0; q < 4; q++) m *= ((i >> (3 - q)) & 1) ? sq[q] : cq[q];
        int k = __popc(i) & 3;  // phase (-i)^k
        re[i] = (k == 0) ? m : ((k == 2) ? -m : 0.f);
        im[i] = (k == 1) ? -m : ((k == 3) ? m : 0.f);
    }

    // ---- BasicEntanglerLayers: RX(w[l,q]) then CNOT ring ----
    #pragma unroll
    for (int l = 0; l < 2; l++) {
        #pragma unroll
        for (int q = 0; q < 4; q++) {
            float cg, sg;
            __sincosf(0.5f * sw[4 + l * 4 + q], &sg, &cg);
            const int mask = 8 >> q;
            #pragma unroll
            for (int i = 0; i < 16; i++) {
                if (i & mask) continue;
                const int i1 = i | mask;
                float r0 = re[i], ii0 = im[i], r1 = re[i1], ii1 = im[i1];
                re[i]  = fmaf(cg, r0,  sg * ii1);
                im[i]  = fmaf(cg, ii0, -sg * r1);
                re[i1] = fmaf(cg, r1,  sg * ii0);
                im[i1] = fmaf(cg, ii1, -sg * r0);
            }
        }
        #pragma unroll
        for (int q = 0; q < 4; q++) {
            const int cmask = 8 >> q;
            const int tmask = 8 >> ((q + 1) & 3);
            #pragma unroll
            for (int i = 0; i < 16; i++) {
                if ((i & cmask) && !(i & tmask)) {
                    const int j = i | tmask;
                    float t = re[i]; re[i] = re[j]; re[j] = t;
                    t = im[i]; im[i] = im[j]; im[j] = t;
                }
            }
        }
    }

    // ---- <Z_q> expectation values ----
    float ez[4] = {0.f, 0.f, 0.f, 0.f};
    #pragma unroll
    for (int i = 0; i < 16; i++) {
        float p = re[i] * re[i] + im[i] * im[i];
        #pragma unroll
        for (int q = 0; q < 4; q++)
            ez[q] += ((i >> (3 - q)) & 1) ? -p : p;
    }
    #pragma unroll
    for (int q = 0; q < 4; q++)
        if (!(ez[q] == ez[q])) ez[q] = 0.f;  // NaN -> 0 (matches reference)

    // ---- post = relu(ez@W2 + b2); logits = post@W3 + b3; softmax ----
    float l0 = sw[236], l1 = sw[237];
    #pragma unroll
    for (int j = 0; j < 32; j++) {
        float pj = sw[140 + j];
        #pragma unroll
        for (int q = 0; q < 4; q++)
            pj = fmaf(ez[q], sw[12 + q * 32 + j], pj);
        pj = fmaxf(pj, 0.f);
        l0 = fmaf(pj, sw[172 + j * 2],     l0);
        l1 = fmaf(pj, sw[172 + j * 2 + 1], l1);
    }
    float mx = fmaxf(l0, l1);
    float e0 = __expf(l0 - mx);
    float e1 = __expf(l1 - mx);
    float inv = 1.f / (e0 + e1);

    long sg = sbase + tid;
    if (sg < (long)B) {
        float2 o = make_float2(e0 * inv, e1 * inv);
        *(float2*)(out + sg * 2) = o;
    }
}

extern "C" void kernel_launch(void* const* d_in, const int* in_sizes, int n_in,
                              void* d_out, int out_size) {
    const float* x  = (const float*)d_in[0];
    const float* W1 = (const float*)d_in[1];
    const float* b1 = (const float*)d_in[2];
    const float* qw = (const float*)d_in[3];
    const float* W2 = (const float*)d_in[4];
    const float* b2 = (const float*)d_in[5];
    const float* W3 = (const float*)d_in[6];
    const float* b3 = (const float*)d_in[7];
    float* out = (float*)d_out;

    int B = in_sizes[0] / KDIM;
    int grid = (B + BLOCKT - 1) / BLOCKT;
    size_t smem_bytes = SMEM_FLOATS * sizeof(float);  // ~49.4 KB -> opt-in
    cudaFuncSetAttribute(qhybrid_kernel,
                         cudaFuncAttributeMaxDynamicSharedMemorySize,
                         (int)smem_bytes);
    qhybrid_kernel<<<grid, BLOCKT, smem_bytes>>>(x, W1, b1, qw, W2, b2, W3, b3, out, B);
}